// round 9
// baseline (speedup 1.0000x reference)
#include <cuda_runtime.h>
#include <cstdint>
#include <math.h>

#define B_   2
#define S_   2048
#define D_   1024
#define H_   16
#define DK_  64
#define NROWS (B_ * S_)   // 4096
#define NWORDS (S_ / 64)  // 32 u64 mask words per row

// Scratch (allocation-free rule: __device__ globals)
__device__ float g_Q[NROWS * D_];     // tf32 bits (pre-scaled by 0.125)
__device__ float g_K[NROWS * D_];     // tf32 bits
__device__ float g_V[NROWS * D_];     // tf32 bits
__device__ float g_Vt[(size_t)B_ * D_ * S_];  // V transposed: [b][dim][token]
__device__ float g_A[NROWS * D_];     // tf32 bits (attention out)
__device__ float g_qc[NROWS * D_];    // pre-converted activations
__device__ float g_kc[NROWS * D_];
__device__ float g_vc[NROWS * D_];
__device__ float g_wq[D_ * D_];       // pre-converted weights
__device__ float g_wk[D_ * D_];
__device__ float g_wv[D_ * D_];
__device__ float g_wo[D_ * D_];
__device__ unsigned long long g_mbits[(size_t)B_ * S_ * NWORDS];  // 1 MB

// ---------------------------------------------------------------------------
// helpers
// ---------------------------------------------------------------------------
__device__ __forceinline__ uint32_t f2tf(float f) {
    uint32_t u;
    asm("cvt.rna.tf32.f32 %0, %1;" : "=r"(u) : "f"(f));
    return u;
}
__device__ __forceinline__ float tfbits(float f) {
    return __uint_as_float(f2tf(f));
}

__device__ __forceinline__ void mma_m16n8k8(float* c, const uint32_t* a,
                                            uint32_t b0, uint32_t b1) {
    asm volatile(
        "mma.sync.aligned.m16n8k8.row.col.f32.tf32.tf32.f32 "
        "{%0,%1,%2,%3}, {%4,%5,%6,%7}, {%8,%9}, {%0,%1,%2,%3};\n"
        : "+f"(c[0]), "+f"(c[1]), "+f"(c[2]), "+f"(c[3])
        : "r"(a[0]), "r"(a[1]), "r"(a[2]), "r"(a[3]), "r"(b0), "r"(b1));
}

// ldmatrix x4: four 8x8 b16 matrices == tf32 fragments (32-bit = b16 pair)
__device__ __forceinline__ void ldsm4(uint32_t* r, uint32_t saddr) {
    asm volatile(
        "ldmatrix.sync.aligned.m8n8.x4.shared.b16 {%0,%1,%2,%3}, [%4];\n"
        : "=r"(r[0]), "=r"(r[1]), "=r"(r[2]), "=r"(r[3]) : "r"(saddr));
}

__device__ __forceinline__ void cp16(void* sdst, const void* gsrc) {
    uint32_t s = (uint32_t)__cvta_generic_to_shared(sdst);
    asm volatile("cp.async.ca.shared.global [%0], [%1], 16;\n" :: "r"(s), "l"(gsrc));
}

// ---------------------------------------------------------------------------
// elementwise fp32 -> tf32-bits (RN) pre-pass
// ---------------------------------------------------------------------------
__global__ void __launch_bounds__(256) cvt_tf32(
    const float* __restrict__ src, float* __restrict__ dst, int n4)
{
    int i = blockIdx.x * blockDim.x + threadIdx.x;
    if (i >= n4) return;
    float4 v = ((const float4*)src)[i];
    v.x = tfbits(v.x); v.y = tfbits(v.y);
    v.z = tfbits(v.z); v.w = tfbits(v.w);
    ((float4*)dst)[i] = v;
}

// ---------------------------------------------------------------------------
// mask [B,1,S,S] int32 -> bit-packed u64
// ---------------------------------------------------------------------------
__global__ void __launch_bounds__(256) pack_mask(
    const int* __restrict__ mask, unsigned long long* __restrict__ bits)
{
    int gw = (int)((blockIdx.x * blockDim.x + threadIdx.x) >> 5);
    int lane = threadIdx.x & 31;
    const int* src = mask + (size_t)gw * 64;
    unsigned lo = __ballot_sync(0xffffffffu, src[lane] != 0);
    unsigned hi = __ballot_sync(0xffffffffu, src[lane + 32] != 0);
    bits[gw] = ((unsigned long long)hi << 32) | lo;
}

// ---------------------------------------------------------------------------
// tiled transpose: g_V [NROWS][D] -> g_Vt [b][d][token]  (coalesced both ways)
// ---------------------------------------------------------------------------
__global__ void __launch_bounds__(256) transpose_v(
    const float* __restrict__ src, float* __restrict__ dst)
{
    __shared__ float tile[32][33];
    int bx = blockIdx.x * 32;   // d
    int by = blockIdx.y * 32;   // global token row
    int tx = threadIdx.x & 31, ty = threadIdx.x >> 5;
    #pragma unroll
    for (int j = 0; j < 32; j += 8)
        tile[ty + j][tx] = src[(size_t)(by + ty + j) * D_ + bx + tx];
    __syncthreads();
    int r = by + tx;                    // token row for this lane
    int b = r >> 11, tok = r & (S_ - 1);
    #pragma unroll
    for (int j = 0; j < 32; j += 8)
        dst[((size_t)(b * D_ + bx + ty + j)) * S_ + tok] = tile[tx][ty + j];
}

// ---------------------------------------------------------------------------
// C[M, Nd] = A[M, K] @ W[Nd, K]^T + bias — tf32 mma + LDSM, 2-stage cp.async.
// Block 128(m) x 256(n), BK=32, 256 threads; warps 2(m) x 4(n), warp 64x64.
// MODE: 0 = fp32 out, 1 = tf32-bits out, 2 = tf32-bits out * 0.125 (exact).
// ---------------------------------------------------------------------------
#define GP 36   // pitch: 36 mod 32 = 4 -> 8 LDSM rows hit distinct banks
#define GP4 (GP * 4)
template <int MODE>
__global__ void __launch_bounds__(256) gemm_tf32(
    const float* __restrict__ A, const float* __restrict__ W,
    const float* __restrict__ bias, float* __restrict__ C,
    int M, int Nd, int K)
{
    extern __shared__ float sm[];
    float* As = sm;                 // 2 * 128 * 36
    float* Bs = sm + 2 * 128 * GP;  // 2 * 256 * 36

    const int tid  = threadIdx.x;
    const int lane = tid & 31, wid = tid >> 5;
    const int g = lane >> 2, t = lane & 3;
    const int wm = (wid >> 2) * 64;   // 0 or 64
    const int wn = (wid & 3) * 64;    // 0,64,128,192
    const int m0 = blockIdx.y * 128, n0 = blockIdx.x * 256;

    // LDSM per-lane address pieces
    const int rowA = lane & 15;
    const int offA = (lane & 16) ? 16 : 0;
    const int rowB = (lane & 7) + ((lane & 16) ? 8 : 0);
    const int offB = (lane & 8) ? 16 : 0;
    const uint32_t As_u = (uint32_t)__cvta_generic_to_shared(As);
    const uint32_t Bs_u = (uint32_t)__cvta_generic_to_shared(Bs);
    const uint32_t aA = (wm + rowA) * GP4 + offA;   // + mt*16*GP4 + ks*32
    const uint32_t aB = (wn + rowB) * GP4 + offB;   // + nt2*16*GP4 + ks*32

    const int k4 = (tid & 7) << 2;  // 0,4,...,28
    const int rb = tid >> 3;        // 0..31

    float acc[4][8][4];
    #pragma unroll
    for (int i = 0; i < 4; i++)
        #pragma unroll
        for (int j = 0; j < 8; j++)
            #pragma unroll
            for (int q = 0; q < 4; q++) acc[i][j][q] = 0.f;

    // prologue: stage 0
    {
        #pragma unroll
        for (int j = 0; j < 4; j++) {
            int r = rb + 32 * j;
            cp16(As + r * GP + k4, A + (size_t)(m0 + r) * K + k4);
        }
        #pragma unroll
        for (int j = 0; j < 8; j++) {
            int r = rb + 32 * j;
            cp16(Bs + r * GP + k4, W + (size_t)(n0 + r) * K + k4);
        }
        asm volatile("cp.async.commit_group;\n");
    }

    const int NS = K / 32;
    for (int s = 0; s < NS; s++) {
        asm volatile("cp.async.wait_group 0;\n");
        __syncthreads();
        if (s + 1 < NS) {
            int kt = (s + 1) * 32;
            float* Ad = As + ((s + 1) & 1) * 128 * GP;
            float* Bd = Bs + ((s + 1) & 1) * 256 * GP;
            #pragma unroll
            for (int j = 0; j < 4; j++) {
                int r = rb + 32 * j;
                cp16(Ad + r * GP + k4, A + (size_t)(m0 + r) * K + kt + k4);
            }
            #pragma unroll
            for (int j = 0; j < 8; j++) {
                int r = rb + 32 * j;
                cp16(Bd + r * GP + k4, W + (size_t)(n0 + r) * K + kt + k4);
            }
            asm volatile("cp.async.commit_group;\n");
        }
        const uint32_t Ab_u = As_u + (s & 1) * 128 * GP4;
        const uint32_t Bb_u = Bs_u + (s & 1) * 256 * GP4;

        #pragma unroll
        for (int ks = 0; ks < 4; ks++) {
            uint32_t af[4][4], bf[8][2];
            #pragma unroll
            for (int mt = 0; mt < 4; mt++)
                ldsm4(af[mt], Ab_u + aA + mt * 16 * GP4 + ks * 32);
            #pragma unroll
            for (int nt2 = 0; nt2 < 4; nt2++) {
                uint32_t bq[4];
                ldsm4(bq, Bb_u + aB + nt2 * 16 * GP4 + ks * 32);
                bf[2 * nt2][0] = bq[0]; bf[2 * nt2][1] = bq[1];
                bf[2 * nt2 + 1][0] = bq[2]; bf[2 * nt2 + 1][1] = bq[3];
            }
            #pragma unroll
            for (int mt = 0; mt < 4; mt++)
                #pragma unroll
                for (int nt = 0; nt < 8; nt++)
                    mma_m16n8k8(acc[mt][nt], af[mt], bf[nt][0], bf[nt][1]);
        }
    }

    // epilogue
    #pragma unroll
    for (int mt = 0; mt < 4; mt++) {
        int r0 = m0 + wm + mt * 16 + g;
        #pragma unroll
        for (int nt = 0; nt < 8; nt++) {
            int c = n0 + wn + nt * 8 + 2 * t;
            float2 bv = *(const float2*)(bias + c);
            float2 o0, o1;
            if (MODE == 0) {
                o0 = make_float2(acc[mt][nt][0] + bv.x, acc[mt][nt][1] + bv.y);
                o1 = make_float2(acc[mt][nt][2] + bv.x, acc[mt][nt][3] + bv.y);
            } else if (MODE == 1) {
                o0 = make_float2(tfbits(acc[mt][nt][0] + bv.x), tfbits(acc[mt][nt][1] + bv.y));
                o1 = make_float2(tfbits(acc[mt][nt][2] + bv.x), tfbits(acc[mt][nt][3] + bv.y));
            } else {
                o0 = make_float2(tfbits(0.125f * (acc[mt][nt][0] + bv.x)),
                                 tfbits(0.125f * (acc[mt][nt][1] + bv.y)));
                o1 = make_float2(tfbits(0.125f * (acc[mt][nt][2] + bv.x)),
                                 tfbits(0.125f * (acc[mt][nt][3] + bv.y)));
            }
            *(float2*)(C + (size_t)r0 * Nd + c)       = o0;
            *(float2*)(C + (size_t)(r0 + 8) * Nd + c) = o1;
        }
    }
}

// ---------------------------------------------------------------------------
// Flash attention, tf32 mma + LDSM everywhere. Br=256, 512 threads = 16 warps,
// 16 q-rows each. K staged [kvrow][k]; V staged TRANSPOSED [dim][token] from
// g_Vt; both LDSM B-pattern. P via LDSM A-pattern. Q pre-scaled by 0.125.
// ---------------------------------------------------------------------------
#define AP 68   // pitch: 68 mod 32 = 4 -> LDSM conflict-free
#define AP4 (AP * 4)
__global__ void __launch_bounds__(512, 1) attn_tf32(
    const float* __restrict__ Qg, const float* __restrict__ Kg,
    const float* __restrict__ Vtg, const unsigned long long* __restrict__ mbits,
    float* __restrict__ O)
{
    extern __shared__ float sm[];
    float* Qs = sm;                       // 256*68
    float* Ps = Qs + 256 * AP;            // 256*68
    float* Ks = Ps + 256 * AP;            // 2 * 64*68
    float* Vs = Ks + 2 * 64 * AP;         // 2 * 64*68

    const int tid = threadIdx.x;
    const int lane = tid & 31, wid = tid >> 5;
    const int g = lane >> 2, t4 = lane & 3;
    const int w16 = wid * 16;
    const int bh = blockIdx.y, b = bh >> 4, h = bh & 15;
    const int q0 = blockIdx.x * 256;
    const int T = S_ / 64;                // 32 KV tiles

    // LDSM per-lane address pieces
    const int rowA = lane & 15;
    const int offA = (lane & 16) ? 16 : 0;
    const int rowB = (lane & 7) + ((lane & 16) ? 8 : 0);
    const int offB = (lane & 8) ? 16 : 0;
    const uint32_t Qs_u = (uint32_t)__cvta_generic_to_shared(Qs);
    const uint32_t Ps_u = (uint32_t)__cvta_generic_to_shared(Ps);
    const uint32_t Ks_u = (uint32_t)__cvta_generic_to_shared(Ks);
    const uint32_t Vs_u = (uint32_t)__cvta_generic_to_shared(Vs);
    const uint32_t aQA = (w16 + rowA) * AP4 + offA;
    const uint32_t aB  = rowB * AP4 + offB;

    const float* Kg0  = Kg  + ((size_t)(b * S_)) * D_ + h * DK_;
    const float* Vtg0 = Vtg + ((size_t)(b * D_ + h * DK_)) * S_;

    // prologue: stage KV tiles 0 and 1
    #pragma unroll
    for (int pt = 0; pt < 2; pt++) {
        const float* Kb  = Kg0  + (size_t)(pt * 64) * D_;
        const float* Vtb = Vtg0 + pt * 64;
        float* Kd = Ks + pt * 64 * AP;
        float* Vd = Vs + pt * 64 * AP;
        #pragma unroll
        for (int i = tid; i < 64 * 16; i += 512) {
            int r = i >> 4, c4 = (i & 15) << 2;
            cp16(Kd + r * AP + c4, Kb  + (size_t)r * D_ + c4);
            cp16(Vd + r * AP + c4, Vtb + (size_t)r * S_ + c4);
        }
        asm volatile("cp.async.commit_group;\n");
    }

    // Q tile [256 x 64] (tf32 bits, pre-scaled) -> smem
    const float* Qb = Qg + ((size_t)(b * S_ + q0)) * D_ + h * DK_;
    for (int i = tid; i < 256 * 16; i += 512) {
        int r = i >> 4, c4 = (i & 15) << 2;
        *(float4*)(Qs + r * AP + c4) = *(const float4*)(Qb + (size_t)r * D_ + c4);
    }
    __syncthreads();

    // Q fragments via LDSM
    uint32_t qf[8][4];
    #pragma unroll
    for (int ks = 0; ks < 8; ks++)
        ldsm4(qf[ks], Qs_u + aQA + ks * 32);

    float oacc[8][4];
    #pragma unroll
    for (int i = 0; i < 8; i++)
        #pragma unroll
        for (int j = 0; j < 4; j++) oacc[i][j] = 0.f;
    float mr0 = -INFINITY, mr1 = -INFINITY, lr0 = 0.f, lr1 = 0.f;

    const unsigned long long* mrow0 =
        mbits + (size_t)(b * S_ + q0 + w16 + g) * NWORDS;
    const unsigned long long* mrow1 =
        mbits + (size_t)(b * S_ + q0 + w16 + g + 8) * NWORDS;

    for (int t = 0; t < T; t++) {
        int s = t & 1;
        unsigned long long mw0 = __ldg(mrow0 + t);
        unsigned long long mw1 = __ldg(mrow1 + t);

        asm volatile("cp.async.wait_group 1;\n");   // tile t landed
        __syncthreads();
        const uint32_t Kb_u = Ks_u + s * 64 * AP4;
        const uint32_t Vb_u = Vs_u + s * 64 * AP4;

        // S = Q K^T (Q pre-scaled); K b-frags via LDSM (2 nt per x4)
        float sacc[8][4];
        #pragma unroll
        for (int i = 0; i < 8; i++)
            #pragma unroll
            for (int j = 0; j < 4; j++) sacc[i][j] = 0.f;
        #pragma unroll
        for (int nt2 = 0; nt2 < 4; nt2++) {
            #pragma unroll
            for (int ks = 0; ks < 8; ks++) {
                uint32_t bq[4];
                ldsm4(bq, Kb_u + aB + nt2 * 16 * AP4 + ks * 32);
                mma_m16n8k8(sacc[2 * nt2],     qf[ks], bq[0], bq[1]);
                mma_m16n8k8(sacc[2 * nt2 + 1], qf[ks], bq[2], bq[3]);
            }
        }

        // mask (bit test) + online softmax
        float rm0 = -INFINITY, rm1 = -INFINITY;
        #pragma unroll
        for (int nt = 0; nt < 8; nt++) {
            int sh = nt * 8 + 2 * t4;
            sacc[nt][0] = ((mw0 >> sh) & 1ull)       ? sacc[nt][0] : -1e9f;
            sacc[nt][1] = ((mw0 >> (sh + 1)) & 1ull) ? sacc[nt][1] : -1e9f;
            sacc[nt][2] = ((mw1 >> sh) & 1ull)       ? sacc[nt][2] : -1e9f;
            sacc[nt][3] = ((mw1 >> (sh + 1)) & 1ull) ? sacc[nt][3] : -1e9f;
            rm0 = fmaxf(rm0, fmaxf(sacc[nt][0], sacc[nt][1]));
            rm1 = fmaxf(rm1, fmaxf(sacc[nt][2], sacc[nt][3]));
        }
        rm0 = fmaxf(rm0, __shfl_xor_sync(0xffffffffu, rm0, 1));
        rm0 = fmaxf(rm0, __shfl_xor_sync(0xffffffffu, rm0, 2));
        rm1 = fmaxf(rm1, __shfl_xor_sync(0xffffffffu, rm1, 1));
        rm1 = fmaxf(rm1, __shfl_xor_sync(0xffffffffu, rm1, 2));

        float mn0 = fmaxf(mr0, rm0), mn1 = fmaxf(mr1, rm1);
        float a0 = __expf(mr0 - mn0), a1 = __expf(mr1 - mn1);
        float rs0 = 0.f, rs1 = 0.f;
        #pragma unroll
        for (int nt = 0; nt < 8; nt++) {
            float p0 = __expf(sacc[nt][0] - mn0);
            float p1 = __expf(sacc[nt][1] - mn0);
            float p2 = __expf(sacc[nt][2] - mn1);
            float p3 = __expf(sacc[nt][3] - mn1);
            rs0 += p0 + p1; rs1 += p2 + p3;
            int c = nt * 8 + 2 * t4;
            float2 lo = make_float2(tfbits(p0), tfbits(p1));
            float2 hi = make_float2(tfbits(p2), tfbits(p3));
            *(float2*)&Ps[(w16 + g)     * AP + c] = lo;
            *(float2*)&Ps[(w16 + g + 8) * AP + c] = hi;
        }
        rs0 += __shfl_xor_sync(0xffffffffu, rs0, 1);
        rs0 += __shfl_xor_sync(0xffffffffu, rs0, 2);
        rs1 += __shfl_xor_sync(0xffffffffu, rs1, 1);
        rs1 += __shfl_xor_sync(0xffffffffu, rs1, 2);
        lr0 = lr0 * a0 + rs0; lr1 = lr1 * a1 + rs1;
        mr0 = mn0; mr1 = mn1;
        #pragma unroll
        for (int nt = 0; nt < 8; nt++) {
            oacc[nt][0] *= a0; oacc[nt][1] *= a0;
            oacc[nt][2] *= a1; oacc[nt][3] *= a1;
        }
        __syncwarp();   // P stores visible to this warp's LDSM reads

        // O += P @ V  (P via LDSM A-pattern; V via LDSM B-pattern on [dim][tok])
        #pragma unroll
        for (int ks = 0; ks < 8; ks++) {
            uint32_t pa[4];
            ldsm4(pa, Ps_u + aQA + ks * 32);
            #pragma unroll
            for (int nt2 = 0; nt2 < 4; nt2++) {
                uint32_t vb[4];
                ldsm4(vb, Vb_u + aB + nt2 * 16 * AP4 + ks * 32);
                mma_m16n8k8(oacc[2 * nt2],     pa, vb[0], vb[1]);
                mma_m16n8k8(oacc[2 * nt2 + 1], pa, vb[2], vb[3]);
            }
        }
        // NOTE: aQA for P uses the same ks*32 column offset — P rows are this
        // warp's 16 rows, k = token within tile.

        __syncthreads();              // all warps done reading stage s
        if (t + 2 < T) {              // refill stage s with tile t+2
            const float* Kb2  = Kg0  + (size_t)((t + 2) * 64) * D_;
            const float* Vtb2 = Vtg0 + (t + 2) * 64;
            float* Kd = Ks + s * 64 * AP;
            float* Vd = Vs + s * 64 * AP;
            #pragma unroll
            for (int i = tid; i < 64 * 16; i += 512) {
                int r = i >> 4, c4 = (i & 15) << 2;
                cp16(Kd + r * AP + c4, Kb2  + (size_t)r * D_ + c4);
                cp16(Vd + r * AP + c4, Vtb2 + (size_t)r * S_ + c4);
            }
        }
        asm volatile("cp.async.commit_group;\n");   // real or empty: uniform accounting
    }

    // write normalized output as tf32 bits (consumed by final GEMM)
    float i0 = 1.f / lr0, i1 = 1.f / lr1;
    #pragma unroll
    for (int nt = 0; nt < 8; nt++) {
        int c = h * DK_ + nt * 8 + 2 * t4;
        size_t r0 = (size_t)(b * S_ + q0 + w16 + g) * D_ + c;
        size_t r1 = (size_t)(b * S_ + q0 + w16 + g + 8) * D_ + c;
        O[r0] = tfbits(oacc[nt][0] * i0); O[r0 + 1] = tfbits(oacc[nt][1] * i0);
        O[r1] = tfbits(oacc[nt][2] * i1); O[r1 + 1] = tfbits(oacc[nt][3] * i1);
    }
}

// ---------------------------------------------------------------------------
extern "C" void kernel_launch(void* const* d_in, const int* in_sizes, int n_in,
                              void* d_out, int out_size)
{
    const float* q    = (const float*)d_in[0];
    const float* k    = (const float*)d_in[1];
    const float* v    = (const float*)d_in[2];
    const int*   mask = (const int*)  d_in[3];
    const float* w_q  = (const float*)d_in[4];
    const float* b_q  = (const float*)d_in[5];
    const float* w_k  = (const float*)d_in[6];
    const float* b_k  = (const float*)d_in[7];
    const float* w_v  = (const float*)d_in[8];
    const float* b_v  = (const float*)d_in[9];
    const float* w_o  = (const float*)d_in[10];
    const float* b_o  = (const float*)d_in[11];
    float* out = (float*)d_out;

    float *Qp, *Kp, *Vp, *Vtp, *Ap, *qc, *kc, *vc, *wq, *wk, *wv, *wo;
    unsigned long long* Mp;
    cudaGetSymbolAddress((void**)&Qp, g_Q);
    cudaGetSymbolAddress((void**)&Kp, g_K);
    cudaGetSymbolAddress((void**)&Vp, g_V);
    cudaGetSymbolAddress((void**)&Vtp, g_Vt);
    cudaGetSymbolAddress((void**)&Ap, g_A);
    cudaGetSymbolAddress((void**)&qc, g_qc);
    cudaGetSymbolAddress((void**)&kc, g_kc);
    cudaGetSymbolAddress((void**)&vc, g_vc);
    cudaGetSymbolAddress((void**)&wq, g_wq);
    cudaGetSymbolAddress((void**)&wk, g_wk);
    cudaGetSymbolAddress((void**)&wv, g_wv);
    cudaGetSymbolAddress((void**)&wo, g_wo);
    cudaGetSymbolAddress((void**)&Mp, g_mbits);

    const int gemm_smem = 2 * (128 + 256) * GP * sizeof(float);   // 110592
    const int attn_smem = (2 * 256 * AP + 4 * 64 * AP) * sizeof(float);  // 208896

    static bool attr_done = false;
    if (!attr_done) {
        cudaFuncSetAttribute(gemm_tf32<0>,
            cudaFuncAttributeMaxDynamicSharedMemorySize, gemm_smem);
        cudaFuncSetAttribute(gemm_tf32<1>,
            cudaFuncAttributeMaxDynamicSharedMemorySize, gemm_smem);
        cudaFuncSetAttribute(gemm_tf32<2>,
            cudaFuncAttributeMaxDynamicSharedMemorySize, gemm_smem);
        cudaFuncSetAttribute(attn_tf32,
            cudaFuncAttributeMaxDynamicSharedMemorySize, attn_smem);
        attr_done = true;
    }

    // pre-passes: mask bit-pack + tf32 conversion of activations/weights
    pack_mask<<<(B_ * S_ * NWORDS) / 8, 256>>>(mask, Mp);
    const int nact4 = NROWS * D_ / 4;
    const int nw4   = D_ * D_ / 4;
    cvt_tf32<<<nact4 / 256, 256>>>(q, qc, nact4);
    cvt_tf32<<<nact4 / 256, 256>>>(k, kc, nact4);
    cvt_tf32<<<nact4 / 256, 256>>>(v, vc, nact4);
    cvt_tf32<<<nw4 / 256, 256>>>(w_q, wq, nw4);
    cvt_tf32<<<nw4 / 256, 256>>>(w_k, wk, nw4);
    cvt_tf32<<<nw4 / 256, 256>>>(w_v, wv, nw4);
    cvt_tf32<<<nw4 / 256, 256>>>(w_o, wo, nw4);

    dim3 gemm_grid(D_ / 256, NROWS / 128);   // (4, 32) = 128 blocks
    gemm_tf32<2><<<gemm_grid, 256, gemm_smem>>>(qc, wq, b_q, Qp, NROWS, D_, D_);
    gemm_tf32<1><<<gemm_grid, 256, gemm_smem>>>(kc, wk, b_k, Kp, NROWS, D_, D_);
    gemm_tf32<1><<<gemm_grid, 256, gemm_smem>>>(vc, wv, b_v, Vp, NROWS, D_, D_);

    transpose_v<<<dim3(D_ / 32, NROWS / 32), 256>>>(Vp, Vtp);

    attn_tf32<<<dim3(S_ / 256, B_ * H_), 512, attn_smem>>>(Qp, Kp, Vtp, Mp, Ap);

    gemm_tf32<0><<<gemm_grid, 256, gemm_smem>>>(Ap, wo, b_o, out, NROWS, D_, D_);
}

// round 10
// speedup vs baseline: 2.3485x; 2.3485x over previous
#include <cuda_runtime.h>
#include <cuda_fp16.h>
#include <cstdint>
#include <math.h>

#define B_   2
#define S_   2048
#define D_   1024
#define H_   16
#define DK_  64
#define NROWS (B_ * S_)   // 4096
#define NWORDS (S_ / 64)  // 32 u64 mask words per row

// Scratch (allocation-free rule: __device__ globals). All fp16.
__device__ __half g_Q[NROWS * D_];            // Q proj, pre-scaled by 0.125
__device__ __half g_K[NROWS * D_];            // K proj
__device__ __half g_Vt[(size_t)D_ * NROWS];   // V proj TRANSPOSED: [dim][b*S+tok]
__device__ __half g_A[NROWS * D_];            // attention out
__device__ __half g_qc[NROWS * D_];           // converted activations
__device__ __half g_kc[NROWS * D_];
__device__ __half g_vc[NROWS * D_];
__device__ __half g_wq[D_ * D_];              // converted weights
__device__ __half g_wk[D_ * D_];
__device__ __half g_wv[D_ * D_];
__device__ __half g_wo[D_ * D_];
__device__ unsigned long long g_mbits[(size_t)B_ * S_ * NWORDS];

// ---------------------------------------------------------------------------
// helpers
// ---------------------------------------------------------------------------
__device__ __forceinline__ void mma_f16(float* c, const uint32_t* a,
                                        uint32_t b0, uint32_t b1) {
    asm volatile(
        "mma.sync.aligned.m16n8k16.row.col.f32.f16.f16.f32 "
        "{%0,%1,%2,%3}, {%4,%5,%6,%7}, {%8,%9}, {%0,%1,%2,%3};\n"
        : "+f"(c[0]), "+f"(c[1]), "+f"(c[2]), "+f"(c[3])
        : "r"(a[0]), "r"(a[1]), "r"(a[2]), "r"(a[3]), "r"(b0), "r"(b1));
}

__device__ __forceinline__ void cp16(void* sdst, const void* gsrc) {
    uint32_t s = (uint32_t)__cvta_generic_to_shared(sdst);
    asm volatile("cp.async.ca.shared.global [%0], [%1], 16;\n" :: "r"(s), "l"(gsrc));
}
__device__ __forceinline__ uint32_t ld32(const __half* p) {
    return *(const uint32_t*)(const void*)p;
}
__device__ __forceinline__ void st32(__half* p, float lo, float hi) {
    __half2 h = __floats2half2_rn(lo, hi);
    *(__half2*)(void*)p = h;
}

// ---------------------------------------------------------------------------
// fp32 -> fp16 (RN) pre-pass: 8 elements per thread
// ---------------------------------------------------------------------------
__global__ void __launch_bounds__(256) cvt_f16(
    const float* __restrict__ src, __half* __restrict__ dst, int n8)
{
    int i = blockIdx.x * blockDim.x + threadIdx.x;
    if (i >= n8) return;
    const float4* s = (const float4*)src;
    float4 a = s[2 * i], b = s[2 * i + 1];
    union { __half2 h[4]; uint4 u; } o;
    o.h[0] = __floats2half2_rn(a.x, a.y);
    o.h[1] = __floats2half2_rn(a.z, a.w);
    o.h[2] = __floats2half2_rn(b.x, b.y);
    o.h[3] = __floats2half2_rn(b.z, b.w);
    ((uint4*)dst)[i] = o.u;
}

// ---------------------------------------------------------------------------
// mask [B,1,S,S] int32 -> bit-packed u64
// ---------------------------------------------------------------------------
__global__ void __launch_bounds__(256) pack_mask(
    const int* __restrict__ mask, unsigned long long* __restrict__ bits)
{
    int gw = (int)((blockIdx.x * blockDim.x + threadIdx.x) >> 5);
    int lane = threadIdx.x & 31;
    const int* src = mask + (size_t)gw * 64;
    unsigned lo = __ballot_sync(0xffffffffu, src[lane] != 0);
    unsigned hi = __ballot_sync(0xffffffffu, src[lane + 32] != 0);
    bits[gw] = ((unsigned long long)hi << 32) | lo;
}

// ---------------------------------------------------------------------------
// C[M, Nd] = A[M, K] @ W[Nd, K]^T + bias — fp16 mma (m16n8k16), 2-stage
// cp.async. Block 128(m) x 256(n), BK=32, 256 threads; warps 2x4, warp 64x64.
// MODE: 0 = fp32 out (col bias)     1 = fp16 out (col bias)
//       2 = fp16 out * 0.125        3 = fp16 out, bias indexed by ROW (used
//           for the transposed V projection: C[dim][tok])
// ---------------------------------------------------------------------------
#define PH 40   // smem pitch in halves (80 B): frag banks (20r+t) mod 32 distinct
template <int MODE>
__global__ void __launch_bounds__(256) gemm_f16(
    const __half* __restrict__ A, const __half* __restrict__ W,
    const float* __restrict__ bias, void* __restrict__ Cv,
    int M, int Nd, int K)
{
    extern __shared__ __half smh[];
    __half* As = smh;                 // 2 * 128 * 40
    __half* Bs = smh + 2 * 128 * PH;  // 2 * 256 * 40

    const int tid  = threadIdx.x;
    const int lane = tid & 31, wid = tid >> 5;
    const int g = lane >> 2, t = lane & 3;
    const int wm = (wid >> 2) * 64;
    const int wn = (wid & 3) * 64;
    const int m0 = blockIdx.y * 128, n0 = blockIdx.x * 256;

    float acc[4][8][4];
    #pragma unroll
    for (int i = 0; i < 4; i++)
        #pragma unroll
        for (int j = 0; j < 8; j++)
            #pragma unroll
            for (int q = 0; q < 4; q++) acc[i][j][q] = 0.f;

    // prologue: stage 0 (BK=32 halves = 4 chunks of 8 halves per row)
    {
        #pragma unroll
        for (int j = 0; j < 2; j++) {
            int idx = tid + 256 * j, r = idx >> 2, ch = (idx & 3) * 8;
            cp16(As + r * PH + ch, A + (size_t)(m0 + r) * K + ch);
        }
        #pragma unroll
        for (int j = 0; j < 4; j++) {
            int idx = tid + 256 * j, r = idx >> 2, ch = (idx & 3) * 8;
            cp16(Bs + r * PH + ch, W + (size_t)(n0 + r) * K + ch);
        }
        asm volatile("cp.async.commit_group;\n");
    }

    const int NS = K / 32;
    for (int s = 0; s < NS; s++) {
        asm volatile("cp.async.wait_group 0;\n");
        __syncthreads();
        if (s + 1 < NS) {
            int kt = (s + 1) * 32;
            __half* Ad = As + ((s + 1) & 1) * 128 * PH;
            __half* Bd = Bs + ((s + 1) & 1) * 256 * PH;
            #pragma unroll
            for (int j = 0; j < 2; j++) {
                int idx = tid + 256 * j, r = idx >> 2, ch = (idx & 3) * 8;
                cp16(Ad + r * PH + ch, A + (size_t)(m0 + r) * K + kt + ch);
            }
            #pragma unroll
            for (int j = 0; j < 4; j++) {
                int idx = tid + 256 * j, r = idx >> 2, ch = (idx & 3) * 8;
                cp16(Bd + r * PH + ch, W + (size_t)(n0 + r) * K + kt + ch);
            }
            asm volatile("cp.async.commit_group;\n");
        }
        const __half* Ab = As + (s & 1) * 128 * PH;
        const __half* Bb = Bs + (s & 1) * 256 * PH;

        #pragma unroll
        for (int ks = 0; ks < 2; ks++) {      // two k16 steps per BK=32
            uint32_t af[4][4], bf[8][2];
            #pragma unroll
            for (int mt = 0; mt < 4; mt++) {
                int r = wm + mt * 16;
                af[mt][0] = ld32(Ab + (r + g)     * PH + ks * 16 + 2 * t);
                af[mt][1] = ld32(Ab + (r + g + 8) * PH + ks * 16 + 2 * t);
                af[mt][2] = ld32(Ab + (r + g)     * PH + ks * 16 + 2 * t + 8);
                af[mt][3] = ld32(Ab + (r + g + 8) * PH + ks * 16 + 2 * t + 8);
            }
            #pragma unroll
            for (int nt = 0; nt < 8; nt++) {
                int c = wn + nt * 8;
                bf[nt][0] = ld32(Bb + (c + g) * PH + ks * 16 + 2 * t);
                bf[nt][1] = ld32(Bb + (c + g) * PH + ks * 16 + 2 * t + 8);
            }
            #pragma unroll
            for (int mt = 0; mt < 4; mt++)
                #pragma unroll
                for (int nt = 0; nt < 8; nt++)
                    mma_f16(acc[mt][nt], af[mt], bf[nt][0], bf[nt][1]);
        }
    }

    // epilogue
    #pragma unroll
    for (int mt = 0; mt < 4; mt++) {
        int r0 = m0 + wm + mt * 16 + g;
        float br0 = 0.f, br8 = 0.f;
        if (MODE == 3) { br0 = bias[r0]; br8 = bias[r0 + 8]; }
        #pragma unroll
        for (int nt = 0; nt < 8; nt++) {
            int c = n0 + wn + nt * 8 + 2 * t;
            if (MODE == 0) {
                float* C = (float*)Cv;
                float2 bv = *(const float2*)(bias + c);
                *(float2*)(C + (size_t)r0 * Nd + c) =
                    make_float2(acc[mt][nt][0] + bv.x, acc[mt][nt][1] + bv.y);
                *(float2*)(C + (size_t)(r0 + 8) * Nd + c) =
                    make_float2(acc[mt][nt][2] + bv.x, acc[mt][nt][3] + bv.y);
            } else if (MODE == 1) {
                __half* C = (__half*)Cv;
                float2 bv = *(const float2*)(bias + c);
                st32(C + (size_t)r0 * Nd + c,
                     acc[mt][nt][0] + bv.x, acc[mt][nt][1] + bv.y);
                st32(C + (size_t)(r0 + 8) * Nd + c,
                     acc[mt][nt][2] + bv.x, acc[mt][nt][3] + bv.y);
            } else if (MODE == 2) {
                __half* C = (__half*)Cv;
                float2 bv = *(const float2*)(bias + c);
                st32(C + (size_t)r0 * Nd + c,
                     0.125f * (acc[mt][nt][0] + bv.x), 0.125f * (acc[mt][nt][1] + bv.y));
                st32(C + (size_t)(r0 + 8) * Nd + c,
                     0.125f * (acc[mt][nt][2] + bv.x), 0.125f * (acc[mt][nt][3] + bv.y));
            } else {   // MODE 3: row bias (transposed V projection)
                __half* C = (__half*)Cv;
                st32(C + (size_t)r0 * Nd + c,
                     acc[mt][nt][0] + br0, acc[mt][nt][1] + br0);
                st32(C + (size_t)(r0 + 8) * Nd + c,
                     acc[mt][nt][2] + br8, acc[mt][nt][3] + br8);
            }
        }
    }
}

// ---------------------------------------------------------------------------
// Flash attention, fp16 mma (m16n8k16). Br=256, 512 threads = 16 warps,
// 16 q-rows each. K staged [tok][kdim]; V staged [dim][tok] straight from
// g_Vt; 2-stage cp.async ring. Q pre-scaled by 0.125. Mask bit-packed.
// ---------------------------------------------------------------------------
#define APH 72   // smem pitch in halves (144 B): frag banks (4g+t) distinct
__global__ void __launch_bounds__(512, 1) attn_f16(
    const __half* __restrict__ Qg, const __half* __restrict__ Kg,
    const __half* __restrict__ Vtg, const unsigned long long* __restrict__ mbits,
    __half* __restrict__ O)
{
    extern __shared__ __half smh[];
    __half* Qs = smh;                       // 256*72
    __half* Ps = Qs + 256 * APH;            // 256*72
    __half* Ks = Ps + 256 * APH;            // 2 * 64*72
    __half* Vs = Ks + 2 * 64 * APH;         // 2 * 64*72

    const int tid = threadIdx.x;
    const int lane = tid & 31, wid = tid >> 5;
    const int g = lane >> 2, t4 = lane & 3;
    const int w16 = wid * 16;
    const int bh = blockIdx.y, b = bh >> 4, h = bh & 15;
    const int q0 = blockIdx.x * 256;
    const int T = S_ / 64;                  // 32 KV tiles

    const __half* Kg0  = Kg  + ((size_t)(b * S_)) * D_ + h * DK_;
    const __half* Vtg0 = Vtg + (size_t)(h * DK_) * NROWS + b * S_;

    // prologue: stage KV tiles 0 and 1 (each row = 64 halves = 8 x 16B chunks)
    #pragma unroll
    for (int pt = 0; pt < 2; pt++) {
        int r = tid >> 3, ch = (tid & 7) * 8;   // 64 rows x 8 chunks = 512
        cp16(Ks + pt * 64 * APH + r * APH + ch,
             Kg0 + (size_t)(pt * 64 + r) * D_ + ch);
        cp16(Vs + pt * 64 * APH + r * APH + ch,
             Vtg0 + (size_t)r * NROWS + pt * 64 + ch);
        asm volatile("cp.async.commit_group;\n");
    }
    // Q tile [256 x 64] halves
    {
        const __half* Qb = Qg + ((size_t)(b * S_ + q0)) * D_ + h * DK_;
        #pragma unroll
        for (int j = 0; j < 4; j++) {
            int idx = tid + 512 * j, r = idx >> 3, ch = (idx & 7) * 8;
            cp16(Qs + r * APH + ch, Qb + (size_t)r * D_ + ch);
        }
        asm volatile("cp.async.commit_group;\n");
    }
    asm volatile("cp.async.wait_group 0;\n");
    __syncthreads();

    // Q fragments (4 k16-steps)
    uint32_t qf[4][4];
    #pragma unroll
    for (int ks = 0; ks < 4; ks++) {
        qf[ks][0] = ld32(Qs + (w16 + g)     * APH + ks * 16 + 2 * t4);
        qf[ks][1] = ld32(Qs + (w16 + g + 8) * APH + ks * 16 + 2 * t4);
        qf[ks][2] = ld32(Qs + (w16 + g)     * APH + ks * 16 + 2 * t4 + 8);
        qf[ks][3] = ld32(Qs + (w16 + g + 8) * APH + ks * 16 + 2 * t4 + 8);
    }

    float oacc[8][4];
    #pragma unroll
    for (int i = 0; i < 8; i++)
        #pragma unroll
        for (int j = 0; j < 4; j++) oacc[i][j] = 0.f;
    float mr0 = -INFINITY, mr1 = -INFINITY, lr0 = 0.f, lr1 = 0.f;

    const unsigned long long* mrow0 =
        mbits + (size_t)(b * S_ + q0 + w16 + g) * NWORDS;
    const unsigned long long* mrow1 =
        mbits + (size_t)(b * S_ + q0 + w16 + g + 8) * NWORDS;

    for (int t = 0; t < T; t++) {
        int s = t & 1;
        unsigned long long mw0 = __ldg(mrow0 + t);
        unsigned long long mw1 = __ldg(mrow1 + t);

        if (t > 0) asm volatile("cp.async.wait_group 1;\n");
        __syncthreads();
        const __half* Kb = Ks + s * 64 * APH;
        const __half* Vb = Vs + s * 64 * APH;

        // S = Q K^T (Q pre-scaled)
        float sacc[8][4];
        #pragma unroll
        for (int i = 0; i < 8; i++)
            #pragma unroll
            for (int j = 0; j < 4; j++) sacc[i][j] = 0.f;
        #pragma unroll
        for (int nt = 0; nt < 8; nt++) {
            #pragma unroll
            for (int ks = 0; ks < 4; ks++) {
                uint32_t b0 = ld32(Kb + (nt * 8 + g) * APH + ks * 16 + 2 * t4);
                uint32_t b1 = ld32(Kb + (nt * 8 + g) * APH + ks * 16 + 2 * t4 + 8);
                mma_f16(sacc[nt], qf[ks], b0, b1);
            }
        }

        // mask (bit test) + online softmax
        float rm0 = -INFINITY, rm1 = -INFINITY;
        #pragma unroll
        for (int nt = 0; nt < 8; nt++) {
            int sh = nt * 8 + 2 * t4;
            sacc[nt][0] = ((mw0 >> sh) & 1ull)       ? sacc[nt][0] : -1e9f;
            sacc[nt][1] = ((mw0 >> (sh + 1)) & 1ull) ? sacc[nt][1] : -1e9f;
            sacc[nt][2] = ((mw1 >> sh) & 1ull)       ? sacc[nt][2] : -1e9f;
            sacc[nt][3] = ((mw1 >> (sh + 1)) & 1ull) ? sacc[nt][3] : -1e9f;
            rm0 = fmaxf(rm0, fmaxf(sacc[nt][0], sacc[nt][1]));
            rm1 = fmaxf(rm1, fmaxf(sacc[nt][2], sacc[nt][3]));
        }
        rm0 = fmaxf(rm0, __shfl_xor_sync(0xffffffffu, rm0, 1));
        rm0 = fmaxf(rm0, __shfl_xor_sync(0xffffffffu, rm0, 2));
        rm1 = fmaxf(rm1, __shfl_xor_sync(0xffffffffu, rm1, 1));
        rm1 = fmaxf(rm1, __shfl_xor_sync(0xffffffffu, rm1, 2));

        float mn0 = fmaxf(mr0, rm0), mn1 = fmaxf(mr1, rm1);
        float a0 = __expf(mr0 - mn0), a1 = __expf(mr1 - mn1);
        float rs0 = 0.f, rs1 = 0.f;
        #pragma unroll
        for (int nt = 0; nt < 8; nt++) {
            float p0 = __expf(sacc[nt][0] - mn0);
            float p1 = __expf(sacc[nt][1] - mn0);
            float p2 = __expf(sacc[nt][2] - mn1);
            float p3 = __expf(sacc[nt][3] - mn1);
            rs0 += p0 + p1; rs1 += p2 + p3;
            int c = nt * 8 + 2 * t4;
            st32(Ps + (w16 + g)     * APH + c, p0, p1);
            st32(Ps + (w16 + g + 8) * APH + c, p2, p3);
        }
        rs0 += __shfl_xor_sync(0xffffffffu, rs0, 1);
        rs0 += __shfl_xor_sync(0xffffffffu, rs0, 2);
        rs1 += __shfl_xor_sync(0xffffffffu, rs1, 1);
        rs1 += __shfl_xor_sync(0xffffffffu, rs1, 2);
        lr0 = lr0 * a0 + rs0; lr1 = lr1 * a1 + rs1;
        mr0 = mn0; mr1 = mn1;
        #pragma unroll
        for (int nt = 0; nt < 8; nt++) {
            oacc[nt][0] *= a0; oacc[nt][1] *= a0;
            oacc[nt][2] *= a1; oacc[nt][3] *= a1;
        }
        __syncwarp();   // P stores visible across lanes of this warp

        // O += P @ V   (P a-frags, V [dim][tok] b-frags; k = token)
        #pragma unroll
        for (int ks = 0; ks < 4; ks++) {
            uint32_t pa[4];
            pa[0] = ld32(Ps + (w16 + g)     * APH + ks * 16 + 2 * t4);
            pa[1] = ld32(Ps + (w16 + g + 8) * APH + ks * 16 + 2 * t4);
            pa[2] = ld32(Ps + (w16 + g)     * APH + ks * 16 + 2 * t4 + 8);
            pa[3] = ld32(Ps + (w16 + g + 8) * APH + ks * 16 + 2 * t4 + 8);
            #pragma unroll
            for (int nt = 0; nt < 8; nt++) {
                uint32_t b0 = ld32(Vb + (nt * 8 + g) * APH + ks * 16 + 2 * t4);
                uint32_t b1 = ld32(Vb + (nt * 8 + g) * APH + ks * 16 + 2 * t4 + 8);
                mma_f16(oacc[nt], pa, b0, b1);
            }
        }

        __syncthreads();              // all warps done reading stage s
        if (t + 2 < T) {              // refill stage s with tile t+2
            int r = tid >> 3, ch = (tid & 7) * 8;
            cp16(Ks + s * 64 * APH + r * APH + ch,
                 Kg0 + (size_t)((t + 2) * 64 + r) * D_ + ch);
            cp16(Vs + s * 64 * APH + r * APH + ch,
                 Vtg0 + (size_t)r * NROWS + (t + 2) * 64 + ch);
        }
        asm volatile("cp.async.commit_group;\n");   // real or empty: uniform accounting
    }

    // write normalized output (fp16, consumed by final GEMM)
    float i0 = 1.f / lr0, i1 = 1.f / lr1;
    #pragma unroll
    for (int nt = 0; nt < 8; nt++) {
        int c = h * DK_ + nt * 8 + 2 * t4;
        size_t r0 = (size_t)(b * S_ + q0 + w16 + g) * D_ + c;
        size_t r1 = (size_t)(b * S_ + q0 + w16 + g + 8) * D_ + c;
        st32(O + r0, oacc[nt][0] * i0, oacc[nt][1] * i0);
        st32(O + r1, oacc[nt][2] * i1, oacc[nt][3] * i1);
    }
}

// ---------------------------------------------------------------------------
extern "C" void kernel_launch(void* const* d_in, const int* in_sizes, int n_in,
                              void* d_out, int out_size)
{
    const float* q    = (const float*)d_in[0];
    const float* k    = (const float*)d_in[1];
    const float* v    = (const float*)d_in[2];
    const int*   mask = (const int*)  d_in[3];
    const float* w_q  = (const float*)d_in[4];
    const float* b_q  = (const float*)d_in[5];
    const float* w_k  = (const float*)d_in[6];
    const float* b_k  = (const float*)d_in[7];
    const float* w_v  = (const float*)d_in[8];
    const float* b_v  = (const float*)d_in[9];
    const float* w_o  = (const float*)d_in[10];
    const float* b_o  = (const float*)d_in[11];
    float* out = (float*)d_out;

    __half *Qp, *Kp, *Vtp, *Ap, *qc, *kc, *vc, *wq, *wk, *wv, *wo;
    unsigned long long* Mp;
    cudaGetSymbolAddress((void**)&Qp, g_Q);
    cudaGetSymbolAddress((void**)&Kp, g_K);
    cudaGetSymbolAddress((void**)&Vtp, g_Vt);
    cudaGetSymbolAddress((void**)&Ap, g_A);
    cudaGetSymbolAddress((void**)&qc, g_qc);
    cudaGetSymbolAddress((void**)&kc, g_kc);
    cudaGetSymbolAddress((void**)&vc, g_vc);
    cudaGetSymbolAddress((void**)&wq, g_wq);
    cudaGetSymbolAddress((void**)&wk, g_wk);
    cudaGetSymbolAddress((void**)&wv, g_wv);
    cudaGetSymbolAddress((void**)&wo, g_wo);
    cudaGetSymbolAddress((void**)&Mp, g_mbits);

    const int gemm_smem = 2 * (128 + 256) * PH * (int)sizeof(__half);   // 61440
    const int attn_smem = (2 * 256 * APH + 4 * 64 * APH) * (int)sizeof(__half); // 110592

    static bool attr_done = false;
    if (!attr_done) {
        cudaFuncSetAttribute(gemm_f16<0>,
            cudaFuncAttributeMaxDynamicSharedMemorySize, gemm_smem);
        cudaFuncSetAttribute(gemm_f16<1>,
            cudaFuncAttributeMaxDynamicSharedMemorySize, gemm_smem);
        cudaFuncSetAttribute(gemm_f16<2>,
            cudaFuncAttributeMaxDynamicSharedMemorySize, gemm_smem);
        cudaFuncSetAttribute(gemm_f16<3>,
            cudaFuncAttributeMaxDynamicSharedMemorySize, gemm_smem);
        cudaFuncSetAttribute(attn_f16,
            cudaFuncAttributeMaxDynamicSharedMemorySize, attn_smem);
        attr_done = true;
    }

    // pre-passes
    pack_mask<<<(B_ * S_ * NWORDS) / 8, 256>>>(mask, Mp);
    const int nact8 = NROWS * D_ / 8;   // 524288
    const int nw8   = D_ * D_ / 8;      // 131072
    cvt_f16<<<nact8 / 256, 256>>>(q, qc, nact8);
    cvt_f16<<<nact8 / 256, 256>>>(k, kc, nact8);
    cvt_f16<<<nact8 / 256, 256>>>(v, vc, nact8);
    cvt_f16<<<nw8 / 256, 256>>>(w_q, wq, nw8);
    cvt_f16<<<nw8 / 256, 256>>>(w_k, wk, nw8);
    cvt_f16<<<nw8 / 256, 256>>>(w_v, wv, nw8);
    cvt_f16<<<nw8 / 256, 256>>>(w_o, wo, nw8);

    // projections
    dim3 gproj(D_ / 256, NROWS / 128);      // (4, 32)
    gemm_f16<2><<<gproj, 256, gemm_smem>>>(qc, wq, b_q, Qp, NROWS, D_, D_);
    gemm_f16<1><<<gproj, 256, gemm_smem>>>(kc, wk, b_k, Kp, NROWS, D_, D_);
    // V projection TRANSPOSED: C[dim][b*S+tok] = W_v A^T + b_v (row bias)
    dim3 gvt(NROWS / 256, D_ / 128);        // (16, 8)
    gemm_f16<3><<<gvt, 256, gemm_smem>>>(wv, vc, b_v, Vtp, D_, NROWS, D_);

    attn_f16<<<dim3(S_ / 256, B_ * H_), 512, attn_smem>>>(Qp, Kp, Vtp, Mp, Ap);

    gemm_f16<0><<<gproj, 256, gemm_smem>>>(Ap, wo, b_o, out, NROWS, D_, D_);
}